// round 2
// baseline (speedup 1.0000x reference)
#include <cuda_runtime.h>
#include <cstdint>

#define BATCH 1024
#define EMB   512
#define NCLS  100000
#define NF4   (NCLS/4)

// ---- margin constants (double-accurate, rounded to f32) ----
#define COS_M_C   0.8775825618903728f
#define SIN_M_C   0.479425538604203f
#define THETA_C  (-0.8775825618903728f)
#define SINMM_C   0.2397127693021015f
#define COS_M1_C  0.9800665778412416f
#define SIN_M1_C  0.19866933079506122f
#define SINMM1_C (-0.039733866159012244f)
#define S_SCALE   64.0f
#define T_P1      1.2f
#define CLEAR_RIO 0.9f

// ---- device scratch (static: no allocations allowed) ----
static __device__ float d_ne[(size_t)BATCH * EMB];           // 2 MB
static __device__ float d_nw[(size_t)NCLS * EMB];            // 204.8 MB
static __device__ float d_ftl[BATCH];
static __device__ float d_ftl1[BATCH];
static __device__ unsigned long long d_hard_cnt;
static __device__ unsigned long long d_noise_cnt;
static __device__ float d_ns;

__device__ __forceinline__ float block128_reduce_sum(float v) {
    #pragma unroll
    for (int o = 16; o > 0; o >>= 1) v += __shfl_down_sync(0xffffffffu, v, o);
    __shared__ float sm[4];
    int t = threadIdx.x;
    if ((t & 31) == 0) sm[t >> 5] = v;
    __syncthreads();
    return sm[0] + sm[1] + sm[2] + sm[3];
}

// ---- 1) row L2-normalize (128 threads/row, one float4 per thread) ----
// NOTE: destination is a __device__ symbol referenced from DEVICE code only.
// (Passing d_ne/d_nw from host as kernel args was the round-1 bug.)
__device__ __forceinline__ void normalize_row_impl(const float* __restrict__ in,
                                                   float* __restrict__ out) {
    int r = blockIdx.x;
    int t = threadIdx.x;
    const float4* ip = reinterpret_cast<const float4*>(in) + (size_t)r * (EMB / 4);
    float4 v = ip[t];
    float s = v.x * v.x + v.y * v.y + v.z * v.z + v.w * v.w;
    float tot = block128_reduce_sum(s);
    float inv = rsqrtf(tot);
    float4* op = reinterpret_cast<float4*>(out) + (size_t)r * (EMB / 4);
    op[t] = make_float4(v.x * inv, v.y * inv, v.z * inv, v.w * inv);
}

__global__ void normalize_emb_kernel(const float* __restrict__ in) {
    normalize_row_impl(in, d_ne);
}
__global__ void normalize_w_kernel(const float* __restrict__ in) {
    normalize_row_impl(in, d_nw);
}

// ---- 2) per-row target logit -> ftl / ftl1; also zero global counters ----
__global__ void prep_kernel(const int* __restrict__ labels) {
    int r = blockIdx.x;
    int t = threadIdx.x;
    if (r == 0 && t == 0) { d_hard_cnt = 0ull; d_noise_cnt = 0ull; }
    int lab = labels[r];
    const float4* a = reinterpret_cast<const float4*>(d_ne) + (size_t)r * (EMB / 4);
    const float4* b = reinterpret_cast<const float4*>(d_nw) + (size_t)lab * (EMB / 4);
    float4 x = a[t], y = b[t];
    float s = x.x * y.x + x.y * y.y + x.z * y.z + x.w * y.w;
    float dot = block128_reduce_sum(s);
    if (t == 0) {
        float tl = fminf(fmaxf(dot, -1.0f), 1.0f);
        float st = sqrtf(1.0f - tl * tl);
        float cos_tm  = tl * COS_M_C  - st * SIN_M_C;
        float cos_tm1 = tl * COS_M1_C - st * SIN_M1_C;
        float ftl  = (tl > THETA_C)   ? cos_tm  : (tl - SINMM_C);
        float ftl1 = (tl <= COS_M1_C) ? cos_tm1 : (tl + SINMM1_C);
        d_ftl[r]  = ftl;
        d_ftl1[r] = ftl1;
    }
}

// ---- 3) fp32 tiled GEMM: logits -> d_out (staged), global mask counts ----
// BM=BN=128, BK=8, 256 threads, 8x8 per thread.
__global__ __launch_bounds__(256, 2) void gemm_count(float* __restrict__ lg) {
    __shared__ float As[8][128];
    __shared__ float Bs[8][128];
    const int tid = threadIdx.x;
    const int n0 = blockIdx.x * 128;
    const int m0 = blockIdx.y * 128;
    const int loadRow = tid >> 1;           // 0..127
    const int loadCol = (tid & 1) * 4;      // 0 or 4
    const int tCol = (tid & 15) * 8;        // 0..120
    const int tRow = (tid >> 4) * 8;        // 0..120

    float acc[8][8];
    #pragma unroll
    for (int i = 0; i < 8; i++)
        #pragma unroll
        for (int j = 0; j < 8; j++) acc[i][j] = 0.0f;

    const float* Aptr = d_ne + (size_t)(m0 + loadRow) * EMB + loadCol;
    const int gn = n0 + loadRow;
    const float* Bptr = d_nw + (size_t)gn * EMB + loadCol;
    const bool bvalid = gn < NCLS;

    for (int k0 = 0; k0 < EMB; k0 += 8) {
        float4 a = *reinterpret_cast<const float4*>(Aptr + k0);
        float4 b = bvalid ? *reinterpret_cast<const float4*>(Bptr + k0)
                          : make_float4(0.f, 0.f, 0.f, 0.f);
        As[loadCol + 0][loadRow] = a.x;
        As[loadCol + 1][loadRow] = a.y;
        As[loadCol + 2][loadRow] = a.z;
        As[loadCol + 3][loadRow] = a.w;
        Bs[loadCol + 0][loadRow] = b.x;
        Bs[loadCol + 1][loadRow] = b.y;
        Bs[loadCol + 2][loadRow] = b.z;
        Bs[loadCol + 3][loadRow] = b.w;
        __syncthreads();
        #pragma unroll
        for (int k = 0; k < 8; k++) {
            float rm[8], rn[8];
            *reinterpret_cast<float4*>(rm)     = *reinterpret_cast<const float4*>(&As[k][tRow]);
            *reinterpret_cast<float4*>(rm + 4) = *reinterpret_cast<const float4*>(&As[k][tRow + 4]);
            *reinterpret_cast<float4*>(rn)     = *reinterpret_cast<const float4*>(&Bs[k][tCol]);
            *reinterpret_cast<float4*>(rn + 4) = *reinterpret_cast<const float4*>(&Bs[k][tCol + 4]);
            #pragma unroll
            for (int i = 0; i < 8; i++)
                #pragma unroll
                for (int j = 0; j < 8; j++)
                    acc[i][j] = fmaf(rm[i], rn[j], acc[i][j]);
        }
        __syncthreads();
    }

    // epilogue: clip, store logits into d_out (staging), count masks
    unsigned int ch = 0, cn = 0;
    #pragma unroll
    for (int i = 0; i < 8; i++) {
        int row = m0 + tRow + i;
        float f  = d_ftl[row];
        float f1 = d_ftl1[row];
        size_t base = (size_t)row * NCLS;
        #pragma unroll
        for (int jj = 0; jj < 2; jj++) {
            int col = n0 + tCol + jj * 4;
            if (col < NCLS) {   // NCLS % 4 == 0, so col+3 < NCLS too
                float4 v;
                v.x = fminf(fmaxf(acc[i][jj * 4 + 0], -1.0f), 1.0f);
                v.y = fminf(fmaxf(acc[i][jj * 4 + 1], -1.0f), 1.0f);
                v.z = fminf(fmaxf(acc[i][jj * 4 + 2], -1.0f), 1.0f);
                v.w = fminf(fmaxf(acc[i][jj * 4 + 3], -1.0f), 1.0f);
                ch += (v.x > f) + (v.y > f) + (v.z > f) + (v.w > f);
                cn += (v.x > f1) + (v.y > f1) + (v.z > f1) + (v.w > f1);
                *reinterpret_cast<float4*>(lg + base + col) = v;
            }
        }
    }
    ch = __reduce_add_sync(0xffffffffu, ch);
    cn = __reduce_add_sync(0xffffffffu, cn);
    __shared__ unsigned int sh[8], sn[8];
    if ((tid & 31) == 0) { sh[tid >> 5] = ch; sn[tid >> 5] = cn; }
    __syncthreads();
    if (tid == 0) {
        unsigned int th = 0, tn = 0;
        #pragma unroll
        for (int w = 0; w < 8; w++) { th += sh[w]; tn += sn[w]; }
        atomicAdd(&d_hard_cnt, (unsigned long long)th);
        atomicAdd(&d_noise_cnt, (unsigned long long)tn);
    }
}

// ---- 4) derive scalars: easy/noise/hard/phi + noise_scale ----
__global__ void scalars_kernel(float* __restrict__ out, long long out_size) {
    unsigned long long hc = d_hard_cnt;
    unsigned long long nc = d_noise_cnt;
    const unsigned long long total = (unsigned long long)BATCH * NCLS;
    unsigned long long easy = total - hc;
    unsigned long long hard = hc - nc;
    float phi = ((float)easy / 102400000.0f) * 0.01f;
    float t = 1.0f - phi / CLEAR_RIO;
    d_ns = t * t;   // GAMMA = 2
    if (out_size >= (long long)total + 4) {
        out[total + 0] = (float)easy;
        out[total + 1] = (float)nc;
        out[total + 2] = (float)hard;
        out[total + 3] = phi;
    }
}

// ---- 5) in-place transform of d_out ----
__global__ void finalize_kernel(float* __restrict__ out, const int* __restrict__ labels) {
    int r = blockIdx.y;
    int idx = blockIdx.x * blockDim.x + threadIdx.x;   // float4 index within row
    if (idx >= NF4) return;
    float ftl  = d_ftl[r];
    float ftl1 = d_ftl1[r];
    float ns   = d_ns;
    int lab = labels[r];
    float4* p = reinterpret_cast<float4*>(out + (size_t)r * NCLS) + idx;
    float4 v = *p;
    int col = idx * 4;
    float xs[4] = {v.x, v.y, v.z, v.w};
    #pragma unroll
    for (int c = 0; c < 4; c++) {
        float x = xs[c];
        float o = x;
        if (x > ftl)  o = x * T_P1;
        if (x > ftl1) o = fmaxf(x * ns, 1e-30f);
        if (col + c == lab) o = ftl;
        xs[c] = o * S_SCALE;
    }
    *p = make_float4(xs[0], xs[1], xs[2], xs[3]);
}

extern "C" void kernel_launch(void* const* d_in, const int* in_sizes, int n_in,
                              void* d_out, int out_size) {
    const float* emb    = (const float*)d_in[0];   // [1024, 512]
    const float* weight = (const float*)d_in[1];   // [100000, 512]
    const int*   labels = (const int*)d_in[2];     // [1024]
    float* out = (float*)d_out;

    normalize_emb_kernel<<<BATCH, 128>>>(emb);
    normalize_w_kernel<<<NCLS, 128>>>(weight);
    prep_kernel<<<BATCH, 128>>>(labels);

    dim3 gg((NCLS + 127) / 128, BATCH / 128);      // 782 x 8
    gemm_count<<<gg, 256>>>(out);

    scalars_kernel<<<1, 1>>>(out, (long long)out_size);

    dim3 fg((NF4 + 255) / 256, BATCH);             // 98 x 1024
    finalize_kernel<<<fg, 256>>>(out, labels);
}

// round 4
// speedup vs baseline: 2.0597x; 2.0597x over previous
#include <cuda_runtime.h>
#include <cuda_fp16.h>
#include <cstdint>

#define BATCH 1024
#define EMB   512
#define NCLS  100000
#define NF4   (NCLS/4)
#define KTOT  1536          // 3 * EMB (K-packed split GEMM)

// ---- margin constants ----
#define COS_M_C   0.8775825618903728f
#define SIN_M_C   0.479425538604203f
#define THETA_C  (-0.8775825618903728f)
#define SINMM_C   0.2397127693021015f
#define COS_M1_C  0.9800665778412416f
#define SIN_M1_C  0.19866933079506122f
#define SINMM1_C (-0.039733866159012244f)
#define S_SCALE   64.0f
#define T_P1      1.2f
#define CLEAR_RIO 0.9f

// ---- device scratch ----
// A' rows: [ah | al | ah], B' rows: [bh | bh | bl]  (fp16 split, K-packed)
static __device__ __align__(16) __half d_neP[(size_t)BATCH * KTOT];   // 3 MB
static __device__ __align__(16) __half d_nwP[(size_t)NCLS * KTOT];    // 300 MB
static __device__ float d_ftl[BATCH];
static __device__ float d_ftl1[BATCH];
static __device__ unsigned long long d_hard_cnt;
static __device__ unsigned long long d_noise_cnt;
static __device__ float d_ns;

__device__ __forceinline__ uint32_t smem_to_u32(const void* p) {
    uint32_t a;
    asm("{ .reg .u64 t; cvta.to.shared.u64 t, %1; cvt.u32.u64 %0, t; }" : "=r"(a) : "l"(p));
    return a;
}

// ================= small kernels =================
__device__ __forceinline__ float block128_reduce_sum(float v) {
    #pragma unroll
    for (int o = 16; o > 0; o >>= 1) v += __shfl_down_sync(0xffffffffu, v, o);
    __shared__ float sm[4];
    int t = threadIdx.x;
    if ((t & 31) == 0) sm[t >> 5] = v;
    __syncthreads();
    return sm[0] + sm[1] + sm[2] + sm[3];
}

// emb: seg0 = h, seg1 = l, seg2 = h
__global__ void normalize_emb_kernel(const float* __restrict__ in) {
    int r = blockIdx.x, t = threadIdx.x;
    const float4* ip = reinterpret_cast<const float4*>(in) + (size_t)r * (EMB / 4);
    float4 v = ip[t];
    float s = v.x * v.x + v.y * v.y + v.z * v.z + v.w * v.w;
    float inv = rsqrtf(block128_reduce_sum(s));
    float xs[4] = {v.x * inv, v.y * inv, v.z * inv, v.w * inv};
    __half h[4], l[4];
    #pragma unroll
    for (int i = 0; i < 4; i++) {
        h[i] = __float2half_rn(xs[i]);
        l[i] = __float2half_rn(xs[i] - __half2float(h[i]));
    }
    size_t base = (size_t)r * KTOT + t * 4;
    *reinterpret_cast<uint2*>(d_neP + base)            = *reinterpret_cast<uint2*>(h);
    *reinterpret_cast<uint2*>(d_neP + base + EMB)      = *reinterpret_cast<uint2*>(l);
    *reinterpret_cast<uint2*>(d_neP + base + 2 * EMB)  = *reinterpret_cast<uint2*>(h);
}

// weight: seg0 = h, seg1 = h, seg2 = l
__global__ void normalize_w_kernel(const float* __restrict__ in) {
    int r = blockIdx.x, t = threadIdx.x;
    const float4* ip = reinterpret_cast<const float4*>(in) + (size_t)r * (EMB / 4);
    float4 v = ip[t];
    float s = v.x * v.x + v.y * v.y + v.z * v.z + v.w * v.w;
    float inv = rsqrtf(block128_reduce_sum(s));
    float xs[4] = {v.x * inv, v.y * inv, v.z * inv, v.w * inv};
    __half h[4], l[4];
    #pragma unroll
    for (int i = 0; i < 4; i++) {
        h[i] = __float2half_rn(xs[i]);
        l[i] = __float2half_rn(xs[i] - __half2float(h[i]));
    }
    size_t base = (size_t)r * KTOT + t * 4;
    *reinterpret_cast<uint2*>(d_nwP + base)            = *reinterpret_cast<uint2*>(h);
    *reinterpret_cast<uint2*>(d_nwP + base + EMB)      = *reinterpret_cast<uint2*>(h);
    *reinterpret_cast<uint2*>(d_nwP + base + 2 * EMB)  = *reinterpret_cast<uint2*>(l);
}

// per-row target logit from RAW inputs; zero counters
__global__ void prep_kernel(const float* __restrict__ emb, const float* __restrict__ w,
                            const int* __restrict__ labels) {
    int r = blockIdx.x, t = threadIdx.x;
    if (r == 0 && t == 0) { d_hard_cnt = 0ull; d_noise_cnt = 0ull; }
    int lab = labels[r];
    const float4* a = reinterpret_cast<const float4*>(emb) + (size_t)r * (EMB / 4);
    const float4* b = reinterpret_cast<const float4*>(w) + (size_t)lab * (EMB / 4);
    float4 x = a[t], y = b[t];
    float sd = x.x * y.x + x.y * y.y + x.z * y.z + x.w * y.w;
    float sa = x.x * x.x + x.y * x.y + x.z * x.z + x.w * x.w;
    float sb = y.x * y.x + y.y * y.y + y.z * y.z + y.w * y.w;
    #pragma unroll
    for (int o = 16; o > 0; o >>= 1) {
        sd += __shfl_down_sync(0xffffffffu, sd, o);
        sa += __shfl_down_sync(0xffffffffu, sa, o);
        sb += __shfl_down_sync(0xffffffffu, sb, o);
    }
    __shared__ float smd[4], sma[4], smb[4];
    if ((t & 31) == 0) { smd[t >> 5] = sd; sma[t >> 5] = sa; smb[t >> 5] = sb; }
    __syncthreads();
    if (t == 0) {
        float dot = smd[0] + smd[1] + smd[2] + smd[3];
        float na  = sma[0] + sma[1] + sma[2] + sma[3];
        float nb  = smb[0] + smb[1] + smb[2] + smb[3];
        float tl = dot * rsqrtf(na) * rsqrtf(nb);
        tl = fminf(fmaxf(tl, -1.0f), 1.0f);
        float st = sqrtf(1.0f - tl * tl);
        float cos_tm  = tl * COS_M_C  - st * SIN_M_C;
        float cos_tm1 = tl * COS_M1_C - st * SIN_M1_C;
        d_ftl[r]  = (tl > THETA_C)   ? cos_tm  : (tl - SINMM_C);
        d_ftl1[r] = (tl <= COS_M1_C) ? cos_tm1 : (tl + SINMM1_C);
    }
}

// ================= mma.sync fp16 GEMM (base-ISA, tensor pipe) =================
// BM=128 BN=128 BK=64, K=1536 (24 iters), 256 threads (8 warps, each 64x32),
// cp.async 4-stage pipeline, swizzled smem + ldmatrix, fused clip/count/store.
#define BM 128
#define BN 128
#define BK 64
#define PIPE 4
#define STG_A (BM * BK * 2)       // 16 KB
#define STG_B (BN * BK * 2)       // 16 KB
#define STG   (STG_A + STG_B)     // 32 KB
#define NKIT  (KTOT / BK)         // 24

#define CP_ASYNC16(dst, src) \
    asm volatile("cp.async.cg.shared.global [%0], [%1], 16;" :: "r"(dst), "l"(src) : "memory")
#define CP_ASYNC16_Z(dst, src, sz) \
    asm volatile("cp.async.cg.shared.global [%0], [%1], 16, %2;" :: "r"(dst), "l"(src), "r"(sz) : "memory")
#define CP_COMMIT() asm volatile("cp.async.commit_group;" ::: "memory")

#define LDSM_X4(r0, r1, r2, r3, a) \
    asm volatile("ldmatrix.sync.aligned.m8n8.x4.shared.b16 {%0,%1,%2,%3}, [%4];" \
                 : "=r"(r0), "=r"(r1), "=r"(r2), "=r"(r3) : "r"(a))

#define MMA16816(c, a, b0r, b1r) \
    asm volatile("mma.sync.aligned.m16n8k16.row.col.f32.f16.f16.f32 " \
                 "{%0,%1,%2,%3}, {%4,%5,%6,%7}, {%8,%9}, {%0,%1,%2,%3};" \
                 : "+f"((c)[0]), "+f"((c)[1]), "+f"((c)[2]), "+f"((c)[3]) \
                 : "r"((a)[0]), "r"((a)[1]), "r"((a)[2]), "r"((a)[3]), "r"(b0r), "r"(b1r))

__global__ __launch_bounds__(256) void gemm_mma(float* __restrict__ lg) {
    extern __shared__ char smem[];
    const uint32_t sbase = smem_to_u32(smem);
    const int tid = threadIdx.x;
    const int wid = tid >> 5;
    const int L = tid & 31;
    const int m0 = blockIdx.x * BM;
    const int n0 = blockIdx.y * BN;
    const int wm = wid & 1;         // 2 warps along M
    const int wn = wid >> 1;        // 4 warps along N

    // ---- cp.async per-thread assignments: 4 A-chunks + 4 B-chunks (16B each) ----
    uint32_t dstOff[4];
    const char* srcA[4];
    const char* srcB[4];
    uint32_t szB[4];
    #pragma unroll
    for (int i = 0; i < 4; i++) {
        int u = tid + i * 256;        // 0..1023
        int row = u >> 3;             // 0..127
        int c = u & 7;                // 16B chunk within 128B row
        dstOff[i] = (uint32_t)(row * 128 + ((c ^ (row & 7)) * 16));
        srcA[i] = (const char*)(d_neP + (size_t)(m0 + row) * KTOT) + c * 16;
        int gn = n0 + row;
        bool valid = gn < NCLS;
        srcB[i] = (const char*)(d_nwP + (size_t)(valid ? gn : 0) * KTOT) + c * 16;
        szB[i] = valid ? 16u : 0u;
    }

    auto issue = [&](int s) {
        const uint32_t b = sbase + s * STG;
        #pragma unroll
        for (int i = 0; i < 4; i++) { CP_ASYNC16(b + dstOff[i], srcA[i]); srcA[i] += BK * 2; }
        #pragma unroll
        for (int i = 0; i < 4; i++) { CP_ASYNC16_Z(b + STG_A + dstOff[i], srcB[i], szB[i]); srcB[i] += BK * 2; }
        CP_COMMIT();
    };

    float acc[4][4][4];
    #pragma unroll
    for (int mi = 0; mi < 4; mi++)
        #pragma unroll
        for (int ni = 0; ni < 4; ni++)
            #pragma unroll
            for (int q = 0; q < 4; q++) acc[mi][ni][q] = 0.0f;

    // ldmatrix lane constants
    const uint32_t laneRowA = (uint32_t)((wm * 64 + (L & 15)) * 128);
    const uint32_t laneRowB = (uint32_t)((wn * 32 + (L & 15)) * 128);
    const uint32_t laneXor = (uint32_t)(L & 7);
    const uint32_t laneCk = (uint32_t)(L >> 4);

    #pragma unroll
    for (int s = 0; s < PIPE - 1; s++) issue(s);

    for (int kt = 0; kt < NKIT; kt++) {
        if (kt + PIPE - 1 < NKIT) {
            asm volatile("cp.async.wait_group %0;" :: "n"(PIPE - 2));
        } else {
            asm volatile("cp.async.wait_group 0;");
        }
        __syncthreads();
        const int s = kt % PIPE;
        const uint32_t Ab = sbase + s * STG;
        const uint32_t Bb = Ab + STG_A;
        if (kt + PIPE - 1 < NKIT) issue((kt + PIPE - 1) % PIPE);

        #pragma unroll
        for (int kc = 0; kc < 4; kc++) {
            const uint32_t ck = ((uint32_t)(kc * 2) + laneCk) ^ laneXor;
            uint32_t a[4][4];
            #pragma unroll
            for (int mi = 0; mi < 4; mi++)
                LDSM_X4(a[mi][0], a[mi][1], a[mi][2], a[mi][3],
                        Ab + laneRowA + mi * 2048 + ck * 16);
            uint32_t bf[2][4];
            #pragma unroll
            for (int np = 0; np < 2; np++)
                LDSM_X4(bf[np][0], bf[np][1], bf[np][2], bf[np][3],
                        Bb + laneRowB + np * 2048 + ck * 16);
            #pragma unroll
            for (int mi = 0; mi < 4; mi++)
                #pragma unroll
                for (int ni = 0; ni < 4; ni++) {
                    const int np = ni >> 1, sel = ni & 1;
                    MMA16816(acc[mi][ni], a[mi], bf[np][sel], bf[np][sel + 2]);
                }
        }
    }

    // ---- epilogue: clip, count masks, store ----
    const int mrow = L >> 2;
    const int ncol = (L & 3) * 2;
    unsigned int ch = 0, cn = 0;
    #pragma unroll
    for (int mi = 0; mi < 4; mi++) {
        const int r0 = m0 + wm * 64 + mi * 16 + mrow;
        const int r1 = r0 + 8;
        const float fa = d_ftl[r0], f1a = d_ftl1[r0];
        const float fb = d_ftl[r1], f1b = d_ftl1[r1];
        const size_t b0 = (size_t)r0 * NCLS;
        const size_t b1 = (size_t)r1 * NCLS;
        #pragma unroll
        for (int ni = 0; ni < 4; ni++) {
            const int col = n0 + wn * 32 + ni * 8 + ncol;
            if (col < NCLS) {    // NCLS % 8 == 0 -> whole pair valid together
                float x0 = fminf(fmaxf(acc[mi][ni][0], -1.0f), 1.0f);
                float x1 = fminf(fmaxf(acc[mi][ni][1], -1.0f), 1.0f);
                float x2 = fminf(fmaxf(acc[mi][ni][2], -1.0f), 1.0f);
                float x3 = fminf(fmaxf(acc[mi][ni][3], -1.0f), 1.0f);
                ch += (x0 > fa) + (x1 > fa) + (x2 > fb) + (x3 > fb);
                cn += (x0 > f1a) + (x1 > f1a) + (x2 > f1b) + (x3 > f1b);
                float2 v0 = make_float2(x0, x1);
                float2 v1 = make_float2(x2, x3);
                *reinterpret_cast<float2*>(lg + b0 + col) = v0;
                *reinterpret_cast<float2*>(lg + b1 + col) = v1;
            }
        }
    }
    ch = __reduce_add_sync(0xffffffffu, ch);
    cn = __reduce_add_sync(0xffffffffu, cn);
    __shared__ unsigned int sh[8], sn[8];
    if (L == 0) { sh[wid] = ch; sn[wid] = cn; }
    __syncthreads();
    if (tid == 0) {
        unsigned int th = 0, tn = 0;
        #pragma unroll
        for (int w = 0; w < 8; w++) { th += sh[w]; tn += sn[w]; }
        atomicAdd(&d_hard_cnt, (unsigned long long)th);
        atomicAdd(&d_noise_cnt, (unsigned long long)tn);
    }
}

// ---- scalars ----
__global__ void scalars_kernel(float* __restrict__ out, long long out_size) {
    unsigned long long hc = d_hard_cnt;
    unsigned long long nc = d_noise_cnt;
    const unsigned long long total = (unsigned long long)BATCH * NCLS;
    unsigned long long easy = total - hc;
    unsigned long long hard = hc - nc;
    float phi = ((float)easy / 102400000.0f) * 0.01f;
    float t = 1.0f - phi / CLEAR_RIO;
    d_ns = t * t;
    if (out_size >= (long long)total + 4) {
        out[total + 0] = (float)easy;
        out[total + 1] = (float)nc;
        out[total + 2] = (float)hard;
        out[total + 3] = phi;
    }
}

// ---- finalize (in-place) ----
__global__ void finalize_kernel(float* __restrict__ out, const int* __restrict__ labels) {
    int r = blockIdx.y;
    int idx = blockIdx.x * blockDim.x + threadIdx.x;
    if (idx >= NF4) return;
    float ftl  = d_ftl[r];
    float ftl1 = d_ftl1[r];
    float ns   = d_ns;
    int lab = labels[r];
    float4* p = reinterpret_cast<float4*>(out + (size_t)r * NCLS) + idx;
    float4 v = *p;
    int col = idx * 4;
    float xs[4] = {v.x, v.y, v.z, v.w};
    #pragma unroll
    for (int c = 0; c < 4; c++) {
        float x = xs[c];
        float o = x;
        if (x > ftl)  o = x * T_P1;
        if (x > ftl1) o = fmaxf(x * ns, 1e-30f);
        if (col + c == lab) o = ftl;
        xs[c] = o * S_SCALE;
    }
    *p = make_float4(xs[0], xs[1], xs[2], xs[3]);
}

extern "C" void kernel_launch(void* const* d_in, const int* in_sizes, int n_in,
                              void* d_out, int out_size) {
    const float* emb    = (const float*)d_in[0];
    const float* weight = (const float*)d_in[1];
    const int*   labels = (const int*)d_in[2];
    float* out = (float*)d_out;

    static const int SMEM_SZ = PIPE * STG;   // 128 KB
    cudaFuncSetAttribute(gemm_mma, cudaFuncAttributeMaxDynamicSharedMemorySize, SMEM_SZ);

    normalize_emb_kernel<<<BATCH, 128>>>(emb);
    normalize_w_kernel<<<NCLS, 128>>>(weight);
    prep_kernel<<<BATCH, 128>>>(emb, weight, labels);

    dim3 gg(BATCH / BM, (NCLS + BN - 1) / BN);   // (8, 782), m fastest -> B-tile L2 reuse
    gemm_mma<<<gg, 256, SMEM_SZ>>>(out);

    scalars_kernel<<<1, 1>>>(out, (long long)out_size);

    dim3 fg((NF4 + 255) / 256, BATCH);
    finalize_kernel<<<fg, 256>>>(out, labels);
}

// round 5
// speedup vs baseline: 2.4697x; 1.1991x over previous
#include <cuda_runtime.h>
#include <cuda_fp16.h>
#include <cstdint>

#define BATCH 1024
#define EMB   512
#define NCLS  100000
#define NF4   (NCLS/4)
#define KTOT  1536          // 3 * EMB (K-packed split GEMM)

// ---- margin constants ----
#define COS_M_C   0.8775825618903728f
#define SIN_M_C   0.479425538604203f
#define THETA_C  (-0.8775825618903728f)
#define SINMM_C   0.2397127693021015f
#define COS_M1_C  0.9800665778412416f
#define SIN_M1_C  0.19866933079506122f
#define SINMM1_C (-0.039733866159012244f)
#define S_SCALE   64.0f
#define T_P1      1.2f
#define CLEAR_RIO 0.9f

// ---- device scratch ----
// A' rows: [ah | al | ah], B' rows: [bh | bh | bl]  (fp16 split, K-packed)
static __device__ __align__(16) __half d_neP[(size_t)BATCH * KTOT];   // 3 MB
static __device__ __align__(16) __half d_nwP[(size_t)NCLS * KTOT];    // 300 MB
static __device__ float d_ftl[BATCH];
static __device__ float d_ftl1[BATCH];
static __device__ unsigned long long d_hard_cnt;
static __device__ unsigned long long d_noise_cnt;
static __device__ float d_ns;

__device__ __forceinline__ uint32_t smem_to_u32(const void* p) {
    uint32_t a;
    asm("{ .reg .u64 t; cvta.to.shared.u64 t, %1; cvt.u32.u64 %0, t; }" : "=r"(a) : "l"(p));
    return a;
}

// ================= small kernels =================
__device__ __forceinline__ float block128_reduce_sum(float v) {
    #pragma unroll
    for (int o = 16; o > 0; o >>= 1) v += __shfl_down_sync(0xffffffffu, v, o);
    __shared__ float sm[4];
    int t = threadIdx.x;
    if ((t & 31) == 0) sm[t >> 5] = v;
    __syncthreads();
    return sm[0] + sm[1] + sm[2] + sm[3];
}

// emb: seg0 = h, seg1 = l, seg2 = h
__global__ void normalize_emb_kernel(const float* __restrict__ in) {
    int r = blockIdx.x, t = threadIdx.x;
    const float4* ip = reinterpret_cast<const float4*>(in) + (size_t)r * (EMB / 4);
    float4 v = ip[t];
    float s = v.x * v.x + v.y * v.y + v.z * v.z + v.w * v.w;
    float inv = rsqrtf(block128_reduce_sum(s));
    float xs[4] = {v.x * inv, v.y * inv, v.z * inv, v.w * inv};
    __half h[4], l[4];
    #pragma unroll
    for (int i = 0; i < 4; i++) {
        h[i] = __float2half_rn(xs[i]);
        l[i] = __float2half_rn(xs[i] - __half2float(h[i]));
    }
    size_t base = (size_t)r * KTOT + t * 4;
    *reinterpret_cast<uint2*>(d_neP + base)            = *reinterpret_cast<uint2*>(h);
    *reinterpret_cast<uint2*>(d_neP + base + EMB)      = *reinterpret_cast<uint2*>(l);
    *reinterpret_cast<uint2*>(d_neP + base + 2 * EMB)  = *reinterpret_cast<uint2*>(h);
}

// weight: seg0 = h, seg1 = h, seg2 = l
__global__ void normalize_w_kernel(const float* __restrict__ in) {
    int r = blockIdx.x, t = threadIdx.x;
    const float4* ip = reinterpret_cast<const float4*>(in) + (size_t)r * (EMB / 4);
    float4 v = ip[t];
    float s = v.x * v.x + v.y * v.y + v.z * v.z + v.w * v.w;
    float inv = rsqrtf(block128_reduce_sum(s));
    float xs[4] = {v.x * inv, v.y * inv, v.z * inv, v.w * inv};
    __half h[4], l[4];
    #pragma unroll
    for (int i = 0; i < 4; i++) {
        h[i] = __float2half_rn(xs[i]);
        l[i] = __float2half_rn(xs[i] - __half2float(h[i]));
    }
    size_t base = (size_t)r * KTOT + t * 4;
    *reinterpret_cast<uint2*>(d_nwP + base)            = *reinterpret_cast<uint2*>(h);
    *reinterpret_cast<uint2*>(d_nwP + base + EMB)      = *reinterpret_cast<uint2*>(h);
    *reinterpret_cast<uint2*>(d_nwP + base + 2 * EMB)  = *reinterpret_cast<uint2*>(l);
}

// per-row target logit from RAW inputs; zero counters
__global__ void prep_kernel(const float* __restrict__ emb, const float* __restrict__ w,
                            const int* __restrict__ labels) {
    int r = blockIdx.x, t = threadIdx.x;
    if (r == 0 && t == 0) { d_hard_cnt = 0ull; d_noise_cnt = 0ull; }
    int lab = labels[r];
    const float4* a = reinterpret_cast<const float4*>(emb) + (size_t)r * (EMB / 4);
    const float4* b = reinterpret_cast<const float4*>(w) + (size_t)lab * (EMB / 4);
    float4 x = a[t], y = b[t];
    float sd = x.x * y.x + x.y * y.y + x.z * y.z + x.w * y.w;
    float sa = x.x * x.x + x.y * x.y + x.z * x.z + x.w * x.w;
    float sb = y.x * y.x + y.y * y.y + y.z * y.z + y.w * y.w;
    #pragma unroll
    for (int o = 16; o > 0; o >>= 1) {
        sd += __shfl_down_sync(0xffffffffu, sd, o);
        sa += __shfl_down_sync(0xffffffffu, sa, o);
        sb += __shfl_down_sync(0xffffffffu, sb, o);
    }
    __shared__ float smd[4], sma[4], smb[4];
    if ((t & 31) == 0) { smd[t >> 5] = sd; sma[t >> 5] = sa; smb[t >> 5] = sb; }
    __syncthreads();
    if (t == 0) {
        float dot = smd[0] + smd[1] + smd[2] + smd[3];
        float na  = sma[0] + sma[1] + sma[2] + sma[3];
        float nb  = smb[0] + smb[1] + smb[2] + smb[3];
        float tl = dot * rsqrtf(na) * rsqrtf(nb);
        tl = fminf(fmaxf(tl, -1.0f), 1.0f);
        float st = sqrtf(1.0f - tl * tl);
        float cos_tm  = tl * COS_M_C  - st * SIN_M_C;
        float cos_tm1 = tl * COS_M1_C - st * SIN_M1_C;
        d_ftl[r]  = (tl > THETA_C)   ? cos_tm  : (tl - SINMM_C);
        d_ftl1[r] = (tl <= COS_M1_C) ? cos_tm1 : (tl + SINMM1_C);
    }
}

// ================= mma.sync fp16 GEMM (base-ISA, tensor pipe) =================
// BM=128 BN=128 BK=64, K=1536 (24 iters), 256 threads (8 warps, each 64x32),
// cp.async 3-stage pipeline (2 CTAs/SM), swizzled smem + ldmatrix,
// register-level double-buffered fragments, fused clip/count/store epilogue.
#define BM 128
#define BN 128
#define BK 64
#define PIPE 3
#define STG_A (BM * BK * 2)       // 16 KB
#define STG_B (BN * BK * 2)       // 16 KB
#define STG   (STG_A + STG_B)     // 32 KB
#define NKIT  (KTOT / BK)         // 24

#define CP_ASYNC16(dst, src) \
    asm volatile("cp.async.cg.shared.global [%0], [%1], 16;" :: "r"(dst), "l"(src) : "memory")
#define CP_ASYNC16_Z(dst, src, sz) \
    asm volatile("cp.async.cg.shared.global [%0], [%1], 16, %2;" :: "r"(dst), "l"(src), "r"(sz) : "memory")
#define CP_COMMIT() asm volatile("cp.async.commit_group;" ::: "memory")

#define LDSM_X4(r0, r1, r2, r3, a) \
    asm volatile("ldmatrix.sync.aligned.m8n8.x4.shared.b16 {%0,%1,%2,%3}, [%4];" \
                 : "=r"(r0), "=r"(r1), "=r"(r2), "=r"(r3) : "r"(a))

#define MMA16816(c, a, b0r, b1r) \
    asm volatile("mma.sync.aligned.m16n8k16.row.col.f32.f16.f16.f32 " \
                 "{%0,%1,%2,%3}, {%4,%5,%6,%7}, {%8,%9}, {%0,%1,%2,%3};" \
                 : "+f"((c)[0]), "+f"((c)[1]), "+f"((c)[2]), "+f"((c)[3]) \
                 : "r"((a)[0]), "r"((a)[1]), "r"((a)[2]), "r"((a)[3]), "r"(b0r), "r"(b1r))

__global__ __launch_bounds__(256, 2) void gemm_mma(float* __restrict__ lg) {
    extern __shared__ char smem[];
    const uint32_t sbase = smem_to_u32(smem);
    const int tid = threadIdx.x;
    const int wid = tid >> 5;
    const int L = tid & 31;
    const int m0 = blockIdx.x * BM;
    const int n0 = blockIdx.y * BN;
    const int wm = wid & 1;         // 2 warps along M
    const int wn = wid >> 1;        // 4 warps along N

    // ---- cp.async per-thread assignments: 4 A-chunks + 4 B-chunks (16B each) ----
    uint32_t dstOff[4];
    const char* srcA[4];
    const char* srcB[4];
    uint32_t szB[4];
    #pragma unroll
    for (int i = 0; i < 4; i++) {
        int u = tid + i * 256;        // 0..1023
        int row = u >> 3;             // 0..127
        int c = u & 7;                // 16B chunk within 128B row
        dstOff[i] = (uint32_t)(row * 128 + ((c ^ (row & 7)) * 16));
        srcA[i] = (const char*)(d_neP + (size_t)(m0 + row) * KTOT) + c * 16;
        int gn = n0 + row;
        bool valid = gn < NCLS;
        srcB[i] = (const char*)(d_nwP + (size_t)(valid ? gn : 0) * KTOT) + c * 16;
        szB[i] = valid ? 16u : 0u;
    }

    auto issue = [&](int s) {
        const uint32_t b = sbase + s * STG;
        #pragma unroll
        for (int i = 0; i < 4; i++) { CP_ASYNC16(b + dstOff[i], srcA[i]); srcA[i] += BK * 2; }
        #pragma unroll
        for (int i = 0; i < 4; i++) { CP_ASYNC16_Z(b + STG_A + dstOff[i], srcB[i], szB[i]); srcB[i] += BK * 2; }
        CP_COMMIT();
    };

    float acc[4][4][4];
    #pragma unroll
    for (int mi = 0; mi < 4; mi++)
        #pragma unroll
        for (int ni = 0; ni < 4; ni++)
            #pragma unroll
            for (int q = 0; q < 4; q++) acc[mi][ni][q] = 0.0f;

    // ldmatrix lane constants
    const uint32_t laneRowA = (uint32_t)((wm * 64 + (L & 15)) * 128);
    const uint32_t laneRowB = (uint32_t)((wn * 32 + (L & 15)) * 128);
    const uint32_t laneXor = (uint32_t)(L & 7);
    const uint32_t laneCk = (uint32_t)(L >> 4);

    #pragma unroll
    for (int s = 0; s < PIPE - 1; s++) issue(s);

    uint32_t a[2][4][4];    // [buf][mi][frag]
    uint32_t bf[2][2][4];   // [buf][np][frag]

    auto ldsm_kc = [&](uint32_t Ab, uint32_t Bb, int kc, int rb) {
        const uint32_t ck = ((uint32_t)(kc * 2) + laneCk) ^ laneXor;
        #pragma unroll
        for (int mi = 0; mi < 4; mi++)
            LDSM_X4(a[rb][mi][0], a[rb][mi][1], a[rb][mi][2], a[rb][mi][3],
                    Ab + laneRowA + mi * 2048 + ck * 16);
        #pragma unroll
        for (int np = 0; np < 2; np++)
            LDSM_X4(bf[rb][np][0], bf[rb][np][1], bf[rb][np][2], bf[rb][np][3],
                    Bb + laneRowB + np * 2048 + ck * 16);
    };
    auto mma_kc = [&](int rb) {
        #pragma unroll
        for (int mi = 0; mi < 4; mi++)
            #pragma unroll
            for (int ni = 0; ni < 4; ni++) {
                const int np = ni >> 1, sel = ni & 1;
                MMA16816(acc[mi][ni], a[rb][mi], bf[rb][np][sel], bf[rb][np][sel + 2]);
            }
    };

    for (int kt = 0; kt < NKIT; kt++) {
        if (kt + PIPE - 1 < NKIT) {
            asm volatile("cp.async.wait_group %0;" :: "n"(PIPE - 2));
        } else {
            asm volatile("cp.async.wait_group 0;");
        }
        __syncthreads();
        const int s = kt % PIPE;
        const uint32_t Ab = sbase + s * STG;
        const uint32_t Bb = Ab + STG_A;
        if (kt + PIPE - 1 < NKIT) issue((kt + PIPE - 1) % PIPE);

        // register-level pipelined kc loop
        ldsm_kc(Ab, Bb, 0, 0);
        #pragma unroll
        for (int kc = 0; kc < 4; kc++) {
            if (kc < 3) ldsm_kc(Ab, Bb, kc + 1, (kc + 1) & 1);
            mma_kc(kc & 1);
        }
    }

    // ---- epilogue: clip, count masks, store ----
    const int mrow = L >> 2;
    const int ncol = (L & 3) * 2;
    unsigned int ch = 0, cn = 0;
    #pragma unroll
    for (int mi = 0; mi < 4; mi++) {
        const int r0 = m0 + wm * 64 + mi * 16 + mrow;
        const int r1 = r0 + 8;
        const float fa = d_ftl[r0], f1a = d_ftl1[r0];
        const float fb = d_ftl[r1], f1b = d_ftl1[r1];
        const size_t b0 = (size_t)r0 * NCLS;
        const size_t b1 = (size_t)r1 * NCLS;
        #pragma unroll
        for (int ni = 0; ni < 4; ni++) {
            const int col = n0 + wn * 32 + ni * 8 + ncol;
            if (col < NCLS) {    // NCLS % 8 == 0 -> whole pair valid together
                float x0 = fminf(fmaxf(acc[mi][ni][0], -1.0f), 1.0f);
                float x1 = fminf(fmaxf(acc[mi][ni][1], -1.0f), 1.0f);
                float x2 = fminf(fmaxf(acc[mi][ni][2], -1.0f), 1.0f);
                float x3 = fminf(fmaxf(acc[mi][ni][3], -1.0f), 1.0f);
                ch += (x0 > fa) + (x1 > fa) + (x2 > fb) + (x3 > fb);
                cn += (x0 > f1a) + (x1 > f1a) + (x2 > f1b) + (x3 > f1b);
                float2 v0 = make_float2(x0, x1);
                float2 v1 = make_float2(x2, x3);
                *reinterpret_cast<float2*>(lg + b0 + col) = v0;
                *reinterpret_cast<float2*>(lg + b1 + col) = v1;
            }
        }
    }
    ch = __reduce_add_sync(0xffffffffu, ch);
    cn = __reduce_add_sync(0xffffffffu, cn);
    __shared__ unsigned int sh[8], sn[8];
    if (L == 0) { sh[wid] = ch; sn[wid] = cn; }
    __syncthreads();
    if (tid == 0) {
        unsigned int th = 0, tn = 0;
        #pragma unroll
        for (int w = 0; w < 8; w++) { th += sh[w]; tn += sn[w]; }
        atomicAdd(&d_hard_cnt, (unsigned long long)th);
        atomicAdd(&d_noise_cnt, (unsigned long long)tn);
    }
}

// ---- scalars ----
__global__ void scalars_kernel(float* __restrict__ out, long long out_size) {
    unsigned long long hc = d_hard_cnt;
    unsigned long long nc = d_noise_cnt;
    const unsigned long long total = (unsigned long long)BATCH * NCLS;
    unsigned long long easy = total - hc;
    unsigned long long hard = hc - nc;
    float phi = ((float)easy / 102400000.0f) * 0.01f;
    float t = 1.0f - phi / CLEAR_RIO;
    d_ns = t * t;
    if (out_size >= (long long)total + 4) {
        out[total + 0] = (float)easy;
        out[total + 1] = (float)nc;
        out[total + 2] = (float)hard;
        out[total + 3] = phi;
    }
}

// ---- finalize (in-place) ----
__global__ void finalize_kernel(float* __restrict__ out, const int* __restrict__ labels) {
    int r = blockIdx.y;
    int idx = blockIdx.x * blockDim.x + threadIdx.x;
    if (idx >= NF4) return;
    float ftl  = d_ftl[r];
    float ftl1 = d_ftl1[r];
    float ns   = d_ns;
    int lab = labels[r];
    float4* p = reinterpret_cast<float4*>(out + (size_t)r * NCLS) + idx;
    float4 v = *p;
    int col = idx * 4;
    float xs[4] = {v.x, v.y, v.z, v.w};
    #pragma unroll
    for (int c = 0; c < 4; c++) {
        float x = xs[c];
        float o = x;
        if (x > ftl)  o = x * T_P1;
        if (x > ftl1) o = fmaxf(x * ns, 1e-30f);
        if (col + c == lab) o = ftl;
        xs[c] = o * S_SCALE;
    }
    *p = make_float4(xs[0], xs[1], xs[2], xs[3]);
}

extern "C" void kernel_launch(void* const* d_in, const int* in_sizes, int n_in,
                              void* d_out, int out_size) {
    const float* emb    = (const float*)d_in[0];
    const float* weight = (const float*)d_in[1];
    const int*   labels = (const int*)d_in[2];
    float* out = (float*)d_out;

    static const int SMEM_SZ = PIPE * STG;   // 96 KB -> 2 CTAs/SM
    cudaFuncSetAttribute(gemm_mma, cudaFuncAttributeMaxDynamicSharedMemorySize, SMEM_SZ);

    normalize_emb_kernel<<<BATCH, 128>>>(emb);
    normalize_w_kernel<<<NCLS, 128>>>(weight);
    prep_kernel<<<BATCH, 128>>>(emb, weight, labels);

    dim3 gg(BATCH / BM, (NCLS + BN - 1) / BN);   // (8, 782), m fastest -> B-tile L2 reuse
    gemm_mma<<<gg, 256, SMEM_SZ>>>(out);

    scalars_kernel<<<1, 1>>>(out, (long long)out_size);

    dim3 fg((NF4 + 255) / 256, BATCH);
    finalize_kernel<<<fg, 256>>>(out, labels);
}